// round 5
// baseline (speedup 1.0000x reference)
#include <cuda_runtime.h>
#include <cuda_bf16.h>

#define N_NODES   50000
#define N_EDGES   800000
#define IN_FEAT   256
#define UNITS     128
#define NEG_SLOPE 0.2f

// ---------------- scratch (device globals; no allocation allowed) ----------
__device__ float g_h[(size_t)N_NODES * UNITS];       // 25.6 MB
__device__ float g_at[N_NODES];
__device__ float g_as[N_NODES];
__device__ float g_scores[N_EDGES];
__device__ float g_denom[N_NODES];
__device__ int   g_edges_i32;   // 1 => edges are int32 pairs, 0 => int64 pairs

// ---------------- packed f32x2 helpers (arithmetic only) -------------------
__device__ __forceinline__ unsigned long long pack2(float lo, float hi) {
    unsigned long long d;
    asm("mov.b64 %0, {%1, %2};" : "=l"(d) : "f"(lo), "f"(hi));
    return d;
}
__device__ __forceinline__ unsigned long long fma2(unsigned long long a,
                                                   unsigned long long b,
                                                   unsigned long long c) {
    unsigned long long d;
    asm("fma.rn.f32x2 %0, %1, %2, %3;" : "=l"(d) : "l"(a), "l"(b), "l"(c));
    return d;
}
__device__ __forceinline__ void unpack2(unsigned long long v, float& lo, float& hi) {
    asm("mov.b64 {%0, %1}, %2;" : "=f"(lo), "=f"(hi) : "l"(v));
}

// fetch edge e as (tgt, src) honoring detected dtype
__device__ __forceinline__ void load_edge(const void* edges, int e,
                                          unsigned int& t, unsigned int& s) {
    if (g_edges_i32) {
        const int2 ed = ((const int2*)edges)[e];
        t = (unsigned int)ed.x; s = (unsigned int)ed.y;
    } else {
        const longlong2 ed = ((const longlong2*)edges)[e];
        t = (unsigned int)ed.x; s = (unsigned int)ed.y;
    }
}

// ---------------- K-1: detect edge dtype ------------------------------------
// int64 indices < 2^31 have zero high words at all odd 32-bit positions;
// int32 (tgt,src) pairs have random src values there.
__global__ void k_detect(const int* __restrict__ ew) {
    __shared__ int any;
    if (threadIdx.x == 0) any = 0;
    __syncthreads();
    for (int i = 2 * threadIdx.x + 1; i < 8192; i += 2 * blockDim.x)
        if (ew[i] != 0) any = 1;               // benign race (only writes 1)
    __syncthreads();
    if (threadIdx.x == 0) g_edges_i32 = any;
}

// ---------------- K0: zero denom + output ----------------------------------
__global__ void k_zero(float* __restrict__ out) {
    const int i = blockIdx.x * blockDim.x + threadIdx.x;
    const int n4 = (N_NODES * UNITS) / 4;
    if (i < n4) ((float4*)out)[i] = make_float4(0.f, 0.f, 0.f, 0.f);
    if (i < N_NODES) g_denom[i] = 0.0f;
}

// ---------------- K1: h = node_states @ kernel  (32-node tiles) ------------
__global__ void __launch_bounds__(128) k_gemm(
    const float* __restrict__ ns,     // [N_NODES, 256]
    const float* __restrict__ kern)   // [256, 128]
{
    __shared__ __align__(16) float s[32 * IN_FEAT];   // 32 KB node tile

    const int nb = blockIdx.x * 32;
    const int j  = threadIdx.x;
    const int rows = min(32, N_NODES - nb);

    {
        const float4* nsv = (const float4*)(ns + (size_t)nb * IN_FEAT);
        float4* sv = (float4*)s;
        const int tot = 32 * (IN_FEAT / 4);
        const int valid = rows * (IN_FEAT / 4);
        for (int idx = j; idx < tot; idx += 128)
            sv[idx] = (idx < valid) ? nsv[idx] : make_float4(0.f, 0.f, 0.f, 0.f);
    }
    __syncthreads();

    unsigned long long acc[32];
#pragma unroll
    for (int i = 0; i < 32; ++i) acc[i] = 0ull;

    for (int k0 = 0; k0 < IN_FEAT; k0 += 4) {
        const float kv0 = kern[(k0 + 0) * UNITS + j];
        const float kv1 = kern[(k0 + 1) * UNITS + j];
        const float kv2 = kern[(k0 + 2) * UNITS + j];
        const float kv3 = kern[(k0 + 3) * UNITS + j];
        const unsigned long long kp01 = pack2(kv0, kv1);
        const unsigned long long kp23 = pack2(kv2, kv3);
#pragma unroll
        for (int i = 0; i < 32; ++i) {
            const ulonglong2 sv = *(const ulonglong2*)&s[i * IN_FEAT + k0];
            acc[i] = fma2(sv.x, kp01, acc[i]);
            acc[i] = fma2(sv.y, kp23, acc[i]);
        }
    }

#pragma unroll
    for (int i = 0; i < 32; ++i) {
        if (i < rows) {
            float lo, hi;
            unpack2(acc[i], lo, hi);
            g_h[(size_t)(nb + i) * UNITS + j] = lo + hi;
        }
    }
}

// ---------------- K2: attention projections a_tgt / a_src ------------------
__global__ void k_attnproj(const float* __restrict__ ka)   // [256]
{
    const int gw   = (blockIdx.x * blockDim.x + threadIdx.x) >> 5;
    const int lane = threadIdx.x & 31;
    if (gw >= N_NODES) return;

    const float4 hv = ((const float4*)(g_h + (size_t)gw * UNITS))[lane];
    const float4 kt = ((const float4*)ka)[lane];
    const float4 ks = ((const float4*)(ka + UNITS))[lane];

    float st = hv.x * kt.x + hv.y * kt.y + hv.z * kt.z + hv.w * kt.w;
    float ss = hv.x * ks.x + hv.y * ks.y + hv.z * ks.z + hv.w * ks.w;
#pragma unroll
    for (int o = 16; o > 0; o >>= 1) {
        st += __shfl_xor_sync(0xffffffffu, st, o);
        ss += __shfl_xor_sync(0xffffffffu, ss, o);
    }
    if (lane == 0) { g_at[gw] = st; g_as[gw] = ss; }
}

// ---------------- K3: edge scores + denominator -----------------------------
__global__ void k_scores(const void* __restrict__ edges)
{
    const int e = blockIdx.x * blockDim.x + threadIdx.x;
    if (e >= N_EDGES) return;
    unsigned int t, s;
    load_edge(edges, e, t, s);
    if (t >= N_NODES || s >= N_NODES) return;       // defensive: never trap
    float x = g_at[t] + g_as[s];
    x = (x > 0.0f) ? x : NEG_SLOPE * x;             // leaky relu
    x = fminf(fmaxf(x, -2.0f), 2.0f);               // clip
    const float sc = __expf(x);
    g_scores[e] = sc;
    atomicAdd(&g_denom[t], sc);
}

// ---------------- K4: weighted scatter-add aggregation ---------------------
__global__ void __launch_bounds__(256) k_aggregate(
    const void* __restrict__ edges,
    float* __restrict__ out)
{
    const int e    = (blockIdx.x * blockDim.x + threadIdx.x) >> 5;
    const int lane = threadIdx.x & 31;
    if (e >= N_EDGES) return;

    unsigned int t, s;
    load_edge(edges, e, t, s);
    if (t >= N_NODES || s >= N_NODES) return;       // defensive: never trap
    const float w = g_scores[e] / g_denom[t];

    const float4 hv = ((const float4*)(g_h + (size_t)s * UNITS))[lane];
    float* dst = out + (size_t)t * UNITS + lane * 4;
    atomicAdd(dst + 0, hv.x * w);
    atomicAdd(dst + 1, hv.y * w);
    atomicAdd(dst + 2, hv.z * w);
    atomicAdd(dst + 3, hv.w * w);
}

// ---------------- launch -----------------------------------------------------
extern "C" void kernel_launch(void* const* d_in, const int* in_sizes, int n_in,
                              void* d_out, int out_size)
{
    // Identify inputs by element count — robust to metadata ordering.
    //   node_states      : 12,800,000 f32
    //   edges            :  1,600,000 (i32 or i64)
    //   kernel           :     32,768 f32
    //   kernel_attention :        256 f32
    const float* ns    = nullptr;
    const void*  edges = nullptr;
    const float* kern  = nullptr;
    const float* ka    = nullptr;
    for (int i = 0; i < n_in; ++i) {
        switch (in_sizes[i]) {
            case 12800000: ns    = (const float*)d_in[i]; break;
            case 1600000:  edges = d_in[i];               break;
            case 32768:    kern  = (const float*)d_in[i]; break;
            case 256:      ka    = (const float*)d_in[i]; break;
        }
    }
    float* out = (float*)d_out;

    k_detect<<<1, 256>>>((const int*)edges);
    k_zero<<<((N_NODES * UNITS) / 4 + 255) / 256, 256>>>(out);
    k_gemm<<<(N_NODES + 31) / 32, 128>>>(ns, kern);
    k_attnproj<<<(N_NODES * 32 + 255) / 256, 256>>>(ka);
    k_scores<<<(N_EDGES + 255) / 256, 256>>>(edges);
    k_aggregate<<<(N_EDGES * 32 + 255) / 256, 256>>>(edges, out);
}

// round 6
// speedup vs baseline: 1.3606x; 1.3606x over previous
#include <cuda_runtime.h>
#include <cuda_bf16.h>

#define N_NODES   50000
#define N_EDGES   800000
#define IN_FEAT   256
#define UNITS     128
#define NEG_SLOPE 0.2f
#define SCAN_T    1024

// ---------------- scratch (device globals) ----------------------------------
__device__ float g_h[(size_t)N_NODES * UNITS];       // 25.6 MB
__device__ float g_at[N_NODES];
__device__ float g_as[N_NODES];
__device__ int   g_count[N_NODES];
__device__ int   g_row_start[N_NODES + 1];
__device__ int   g_row_cur[N_NODES];
__device__ int   g_csr_src[N_EDGES];                  // 3.2 MB
__device__ int   g_edges_i32;   // 1 => int32 pairs, 0 => int64 pairs

// ---------------- packed f32x2 helpers (arithmetic only) -------------------
__device__ __forceinline__ unsigned long long pack2(float lo, float hi) {
    unsigned long long d;
    asm("mov.b64 %0, {%1, %2};" : "=l"(d) : "f"(lo), "f"(hi));
    return d;
}
__device__ __forceinline__ unsigned long long fma2(unsigned long long a,
                                                   unsigned long long b,
                                                   unsigned long long c) {
    unsigned long long d;
    asm("fma.rn.f32x2 %0, %1, %2, %3;" : "=l"(d) : "l"(a), "l"(b), "l"(c));
    return d;
}
__device__ __forceinline__ void unpack2(unsigned long long v, float& lo, float& hi) {
    asm("mov.b64 {%0, %1}, %2;" : "=f"(lo), "=f"(hi) : "l"(v));
}

__device__ __forceinline__ void load_edge(const void* edges, int e,
                                          unsigned int& t, unsigned int& s) {
    if (g_edges_i32) {
        const int2 ed = ((const int2*)edges)[e];
        t = (unsigned int)ed.x; s = (unsigned int)ed.y;
    } else {
        const longlong2 ed = ((const longlong2*)edges)[e];
        t = (unsigned int)ed.x; s = (unsigned int)ed.y;
    }
}

// ---------------- K-1: detect edge dtype ------------------------------------
__global__ void k_detect(const int* __restrict__ ew) {
    __shared__ int any;
    if (threadIdx.x == 0) any = 0;
    __syncthreads();
    for (int i = 2 * threadIdx.x + 1; i < 8192; i += 2 * blockDim.x)
        if (ew[i] != 0) any = 1;
    __syncthreads();
    if (threadIdx.x == 0) g_edges_i32 = any;
}

// ---------------- K0: zero degree counters ----------------------------------
__global__ void k_zero_cnt() {
    const int i = blockIdx.x * blockDim.x + threadIdx.x;
    if (i < N_NODES) g_count[i] = 0;
}

// ---------------- CSR build: histogram -> scan -> scatter -------------------
__global__ void k_hist(const void* __restrict__ edges) {
    const int e = blockIdx.x * blockDim.x + threadIdx.x;
    if (e >= N_EDGES) return;
    unsigned int t, s;
    load_edge(edges, e, t, s);
    if (t >= N_NODES) return;
    atomicAdd(&g_count[t], 1);
}

// single-block exclusive scan of g_count into g_row_start / g_row_cur
__global__ void __launch_bounds__(SCAN_T) k_scan() {
    __shared__ int ssum[SCAN_T];
    const int tid = threadIdx.x;
    const int per = (N_NODES + SCAN_T - 1) / SCAN_T;   // 49
    const int base = tid * per;

    int local = 0;
    for (int i = 0; i < per; ++i) {
        const int idx = base + i;
        if (idx < N_NODES) local += g_count[idx];
    }
    ssum[tid] = local;
    __syncthreads();
    // Hillis-Steele inclusive scan
    for (int off = 1; off < SCAN_T; off <<= 1) {
        int v = (tid >= off) ? ssum[tid - off] : 0;
        __syncthreads();
        ssum[tid] += v;
        __syncthreads();
    }
    int running = (tid == 0) ? 0 : ssum[tid - 1];      // exclusive offset
    for (int i = 0; i < per; ++i) {
        const int idx = base + i;
        if (idx < N_NODES) {
            g_row_start[idx] = running;
            g_row_cur[idx]   = running;
            running += g_count[idx];
        }
    }
    if (tid == SCAN_T - 1) g_row_start[N_NODES] = running;
}

__global__ void k_scatter(const void* __restrict__ edges) {
    const int e = blockIdx.x * blockDim.x + threadIdx.x;
    if (e >= N_EDGES) return;
    unsigned int t, s;
    load_edge(edges, e, t, s);
    if (t >= N_NODES || s >= N_NODES) return;
    const int pos = atomicAdd(&g_row_cur[t], 1);
    g_csr_src[pos] = (int)s;
}

// ---------------- K1: h = node_states @ kernel  (32-node tiles) ------------
__global__ void __launch_bounds__(128) k_gemm(
    const float* __restrict__ ns,     // [N_NODES, 256]
    const float* __restrict__ kern)   // [256, 128]
{
    __shared__ __align__(16) float s[32 * IN_FEAT];

    const int nb = blockIdx.x * 32;
    const int j  = threadIdx.x;
    const int rows = min(32, N_NODES - nb);

    {
        const float4* nsv = (const float4*)(ns + (size_t)nb * IN_FEAT);
        float4* sv = (float4*)s;
        const int tot = 32 * (IN_FEAT / 4);
        const int valid = rows * (IN_FEAT / 4);
        for (int idx = j; idx < tot; idx += 128)
            sv[idx] = (idx < valid) ? nsv[idx] : make_float4(0.f, 0.f, 0.f, 0.f);
    }
    __syncthreads();

    unsigned long long acc[32];
#pragma unroll
    for (int i = 0; i < 32; ++i) acc[i] = 0ull;

    for (int k0 = 0; k0 < IN_FEAT; k0 += 4) {
        const float kv0 = kern[(k0 + 0) * UNITS + j];
        const float kv1 = kern[(k0 + 1) * UNITS + j];
        const float kv2 = kern[(k0 + 2) * UNITS + j];
        const float kv3 = kern[(k0 + 3) * UNITS + j];
        const unsigned long long kp01 = pack2(kv0, kv1);
        const unsigned long long kp23 = pack2(kv2, kv3);
#pragma unroll
        for (int i = 0; i < 32; ++i) {
            const ulonglong2 sv = *(const ulonglong2*)&s[i * IN_FEAT + k0];
            acc[i] = fma2(sv.x, kp01, acc[i]);
            acc[i] = fma2(sv.y, kp23, acc[i]);
        }
    }

#pragma unroll
    for (int i = 0; i < 32; ++i) {
        if (i < rows) {
            float lo, hi;
            unpack2(acc[i], lo, hi);
            g_h[(size_t)(nb + i) * UNITS + j] = lo + hi;
        }
    }
}

// ---------------- K2: attention projections a_tgt / a_src ------------------
__global__ void k_attnproj(const float* __restrict__ ka)
{
    const int gw   = (blockIdx.x * blockDim.x + threadIdx.x) >> 5;
    const int lane = threadIdx.x & 31;
    if (gw >= N_NODES) return;

    const float4 hv = ((const float4*)(g_h + (size_t)gw * UNITS))[lane];
    const float4 kt = ((const float4*)ka)[lane];
    const float4 ks = ((const float4*)(ka + UNITS))[lane];

    float st = hv.x * kt.x + hv.y * kt.y + hv.z * kt.z + hv.w * kt.w;
    float ss = hv.x * ks.x + hv.y * ks.y + hv.z * ks.z + hv.w * ks.w;
#pragma unroll
    for (int o = 16; o > 0; o >>= 1) {
        st += __shfl_xor_sync(0xffffffffu, st, o);
        ss += __shfl_xor_sync(0xffffffffu, ss, o);
    }
    if (lane == 0) { g_at[gw] = st; g_as[gw] = ss; }
}

// ---------------- K4: CSR aggregate — one warp per target node -------------
// acc = sum_e score_e * h[src_e]; denom = sum_e score_e; out = acc/denom.
// No atomics: single coalesced float4 store per lane.
__global__ void __launch_bounds__(256) k_aggregate(float* __restrict__ out)
{
    const int t    = (blockIdx.x * blockDim.x + threadIdx.x) >> 5;
    const int lane = threadIdx.x & 31;
    if (t >= N_NODES) return;

    const int beg = g_row_start[t];
    const int end = g_row_start[t + 1];
    const float at_t = g_at[t];

    float4 acc = make_float4(0.f, 0.f, 0.f, 0.f);
    float denom = 0.f;

    for (int i = beg; i < end; ++i) {
        const int s = g_csr_src[i];
        float x = at_t + g_as[s];
        x = (x > 0.0f) ? x : NEG_SLOPE * x;
        x = fminf(fmaxf(x, -2.0f), 2.0f);
        const float sc = __expf(x);
        const float4 hv = ((const float4*)(g_h + (size_t)s * UNITS))[lane];
        acc.x = fmaf(sc, hv.x, acc.x);
        acc.y = fmaf(sc, hv.y, acc.y);
        acc.z = fmaf(sc, hv.z, acc.z);
        acc.w = fmaf(sc, hv.w, acc.w);
        denom += sc;
    }

    const float inv = (end > beg) ? (1.0f / denom) : 0.0f;
    float4 o;
    o.x = acc.x * inv; o.y = acc.y * inv; o.z = acc.z * inv; o.w = acc.w * inv;
    ((float4*)(out + (size_t)t * UNITS))[lane] = o;
}

// ---------------- launch -----------------------------------------------------
extern "C" void kernel_launch(void* const* d_in, const int* in_sizes, int n_in,
                              void* d_out, int out_size)
{
    const float* ns    = nullptr;
    const void*  edges = nullptr;
    const float* kern  = nullptr;
    const float* ka    = nullptr;
    for (int i = 0; i < n_in; ++i) {
        switch (in_sizes[i]) {
            case 12800000: ns    = (const float*)d_in[i]; break;
            case 1600000:  edges = d_in[i];               break;
            case 32768:    kern  = (const float*)d_in[i]; break;
            case 256:      ka    = (const float*)d_in[i]; break;
        }
    }
    float* out = (float*)d_out;

    k_detect<<<1, 256>>>((const int*)edges);
    k_zero_cnt<<<(N_NODES + 255) / 256, 256>>>();
    k_hist<<<(N_EDGES + 255) / 256, 256>>>(edges);
    k_scan<<<1, SCAN_T>>>();
    k_scatter<<<(N_EDGES + 255) / 256, 256>>>(edges);

    k_gemm<<<(N_NODES + 31) / 32, 128>>>(ns, kern);
    k_attnproj<<<(N_NODES * 32 + 255) / 256, 256>>>(ka);

    k_aggregate<<<(N_NODES * 32 + 255) / 256, 256>>>(out);
}

// round 7
// speedup vs baseline: 1.8325x; 1.3468x over previous
#include <cuda_runtime.h>
#include <cuda_bf16.h>

#define N_NODES   50000
#define N_EDGES   800000
#define IN_FEAT   256
#define UNITS     128
#define NEG_SLOPE 0.2f

#define SCAN_B    256
#define SCAN_NB   ((N_NODES + SCAN_B - 1) / SCAN_B)    // 196

// ---------------- scratch (device globals) ----------------------------------
__device__ float g_h[(size_t)N_NODES * UNITS];       // 25.6 MB
__device__ float g_at[N_NODES];
__device__ float g_as[N_NODES];
__device__ int   g_count[N_NODES];
__device__ int   g_row_start[N_NODES + 1];
__device__ int   g_row_cur[N_NODES];
__device__ int   g_csr_src[N_EDGES];                  // 3.2 MB
__device__ int   g_bsum[SCAN_NB];
__device__ int   g_boff[SCAN_NB];
__device__ int   g_edges_i32;   // 1 => int32 pairs, 0 => int64 pairs

// ---------------- packed f32x2 helpers (arithmetic only) -------------------
__device__ __forceinline__ unsigned long long pack2(float lo, float hi) {
    unsigned long long d;
    asm("mov.b64 %0, {%1, %2};" : "=l"(d) : "f"(lo), "f"(hi));
    return d;
}
__device__ __forceinline__ unsigned long long fma2(unsigned long long a,
                                                   unsigned long long b,
                                                   unsigned long long c) {
    unsigned long long d;
    asm("fma.rn.f32x2 %0, %1, %2, %3;" : "=l"(d) : "l"(a), "l"(b), "l"(c));
    return d;
}
__device__ __forceinline__ void unpack2(unsigned long long v, float& lo, float& hi) {
    asm("mov.b64 {%0, %1}, %2;" : "=f"(lo), "=f"(hi) : "l"(v));
}

__device__ __forceinline__ void load_edge(const void* edges, int e,
                                          unsigned int& t, unsigned int& s) {
    if (g_edges_i32) {
        const int2 ed = ((const int2*)edges)[e];
        t = (unsigned int)ed.x; s = (unsigned int)ed.y;
    } else {
        const longlong2 ed = ((const longlong2*)edges)[e];
        t = (unsigned int)ed.x; s = (unsigned int)ed.y;
    }
}

// ---------------- K-1: detect edge dtype ------------------------------------
__global__ void k_detect(const int* __restrict__ ew) {
    __shared__ int any;
    if (threadIdx.x == 0) any = 0;
    __syncthreads();
    for (int i = 2 * threadIdx.x + 1; i < 8192; i += 2 * blockDim.x)
        if (ew[i] != 0) any = 1;
    __syncthreads();
    if (threadIdx.x == 0) g_edges_i32 = any;
}

// ---------------- K0: zero degree counters ----------------------------------
__global__ void k_zero_cnt() {
    const int i = blockIdx.x * blockDim.x + threadIdx.x;
    if (i < N_NODES) g_count[i] = 0;
}

// ---------------- CSR build: histogram -> 2-level scan -> scatter -----------
__global__ void k_hist(const void* __restrict__ edges) {
    const int e = blockIdx.x * blockDim.x + threadIdx.x;
    if (e >= N_EDGES) return;
    unsigned int t, s;
    load_edge(edges, e, t, s);
    if (t >= N_NODES) return;
    atomicAdd(&g_count[t], 1);
}

// Phase A: block-local exclusive scan, emit block sums
__global__ void __launch_bounds__(SCAN_B) k_scanA() {
    __shared__ int sh[SCAN_B];
    const int tid = threadIdx.x;
    const int gid = blockIdx.x * SCAN_B + tid;
    const int v = (gid < N_NODES) ? g_count[gid] : 0;
    sh[tid] = v;
    __syncthreads();
    int acc = v;
#pragma unroll
    for (int off = 1; off < SCAN_B; off <<= 1) {
        int x = (tid >= off) ? sh[tid - off] : 0;
        __syncthreads();
        acc += x;
        sh[tid] = acc;
        __syncthreads();
    }
    if (gid < N_NODES) g_row_start[gid] = acc - v;     // local exclusive
    if (tid == SCAN_B - 1) g_bsum[blockIdx.x] = acc;   // block total
}

// Phase B: single small block scans the 196 block sums (exclusive)
__global__ void __launch_bounds__(SCAN_B) k_scanB() {
    __shared__ int sh[SCAN_B];
    const int tid = threadIdx.x;
    const int v = (tid < SCAN_NB) ? g_bsum[tid] : 0;
    sh[tid] = v;
    __syncthreads();
    int acc = v;
#pragma unroll
    for (int off = 1; off < SCAN_B; off <<= 1) {
        int x = (tid >= off) ? sh[tid - off] : 0;
        __syncthreads();
        acc += x;
        sh[tid] = acc;
        __syncthreads();
    }
    if (tid < SCAN_NB) g_boff[tid] = acc - v;
    if (tid == SCAN_B - 1) g_row_start[N_NODES] = sh[SCAN_B - 1]; // total = N_EDGES
}

// Phase C: add block offsets, mirror into row_cur
__global__ void __launch_bounds__(SCAN_B) k_scanC() {
    const int gid = blockIdx.x * SCAN_B + threadIdx.x;
    if (gid >= N_NODES) return;
    const int v = g_row_start[gid] + g_boff[blockIdx.x];
    g_row_start[gid] = v;
    g_row_cur[gid]   = v;
}

__global__ void k_scatter(const void* __restrict__ edges) {
    const int e = blockIdx.x * blockDim.x + threadIdx.x;
    if (e >= N_EDGES) return;
    unsigned int t, s;
    load_edge(edges, e, t, s);
    if (t >= N_NODES || s >= N_NODES) return;
    const int pos = atomicAdd(&g_row_cur[t], 1);
    g_csr_src[pos] = (int)s;
}

// ---------------- K1: h = node_states @ kernel  (32-node tiles) ------------
__global__ void __launch_bounds__(128) k_gemm(
    const float* __restrict__ ns,     // [N_NODES, 256]
    const float* __restrict__ kern)   // [256, 128]
{
    __shared__ __align__(16) float s[32 * IN_FEAT];

    const int nb = blockIdx.x * 32;
    const int j  = threadIdx.x;
    const int rows = min(32, N_NODES - nb);

    {
        const float4* nsv = (const float4*)(ns + (size_t)nb * IN_FEAT);
        float4* sv = (float4*)s;
        const int tot = 32 * (IN_FEAT / 4);
        const int valid = rows * (IN_FEAT / 4);
        for (int idx = j; idx < tot; idx += 128)
            sv[idx] = (idx < valid) ? nsv[idx] : make_float4(0.f, 0.f, 0.f, 0.f);
    }
    __syncthreads();

    unsigned long long acc[32];
#pragma unroll
    for (int i = 0; i < 32; ++i) acc[i] = 0ull;

    for (int k0 = 0; k0 < IN_FEAT; k0 += 4) {
        const float kv0 = kern[(k0 + 0) * UNITS + j];
        const float kv1 = kern[(k0 + 1) * UNITS + j];
        const float kv2 = kern[(k0 + 2) * UNITS + j];
        const float kv3 = kern[(k0 + 3) * UNITS + j];
        const unsigned long long kp01 = pack2(kv0, kv1);
        const unsigned long long kp23 = pack2(kv2, kv3);
#pragma unroll
        for (int i = 0; i < 32; ++i) {
            const ulonglong2 sv = *(const ulonglong2*)&s[i * IN_FEAT + k0];
            acc[i] = fma2(sv.x, kp01, acc[i]);
            acc[i] = fma2(sv.y, kp23, acc[i]);
        }
    }

#pragma unroll
    for (int i = 0; i < 32; ++i) {
        if (i < rows) {
            float lo, hi;
            unpack2(acc[i], lo, hi);
            g_h[(size_t)(nb + i) * UNITS + j] = lo + hi;
        }
    }
}

// ---------------- K2: attention projections a_tgt / a_src ------------------
__global__ void k_attnproj(const float* __restrict__ ka)
{
    const int gw   = (blockIdx.x * blockDim.x + threadIdx.x) >> 5;
    const int lane = threadIdx.x & 31;
    if (gw >= N_NODES) return;

    const float4 hv = ((const float4*)(g_h + (size_t)gw * UNITS))[lane];
    const float4 kt = ((const float4*)ka)[lane];
    const float4 ks = ((const float4*)(ka + UNITS))[lane];

    float st = hv.x * kt.x + hv.y * kt.y + hv.z * kt.z + hv.w * kt.w;
    float ss = hv.x * ks.x + hv.y * ks.y + hv.z * ks.z + hv.w * ks.w;
#pragma unroll
    for (int o = 16; o > 0; o >>= 1) {
        st += __shfl_xor_sync(0xffffffffu, st, o);
        ss += __shfl_xor_sync(0xffffffffu, ss, o);
    }
    if (lane == 0) { g_at[gw] = st; g_as[gw] = ss; }
}

// ---------------- K4: CSR aggregate — one warp per target node -------------
__global__ void __launch_bounds__(256) k_aggregate(float* __restrict__ out)
{
    const int t    = (blockIdx.x * blockDim.x + threadIdx.x) >> 5;
    const int lane = threadIdx.x & 31;
    if (t >= N_NODES) return;

    const int beg = g_row_start[t];
    const int end = g_row_start[t + 1];
    const float at_t = g_at[t];

    float4 acc = make_float4(0.f, 0.f, 0.f, 0.f);
    float denom = 0.f;

    for (int i = beg; i < end; ++i) {
        const int s = g_csr_src[i];
        float x = at_t + g_as[s];
        x = (x > 0.0f) ? x : NEG_SLOPE * x;
        x = fminf(fmaxf(x, -2.0f), 2.0f);
        const float sc = __expf(x);
        const float4 hv = ((const float4*)(g_h + (size_t)s * UNITS))[lane];
        acc.x = fmaf(sc, hv.x, acc.x);
        acc.y = fmaf(sc, hv.y, acc.y);
        acc.z = fmaf(sc, hv.z, acc.z);
        acc.w = fmaf(sc, hv.w, acc.w);
        denom += sc;
    }

    const float inv = (end > beg) ? (1.0f / denom) : 0.0f;
    float4 o;
    o.x = acc.x * inv; o.y = acc.y * inv; o.z = acc.z * inv; o.w = acc.w * inv;
    ((float4*)(out + (size_t)t * UNITS))[lane] = o;
}

// ---------------- launch -----------------------------------------------------
extern "C" void kernel_launch(void* const* d_in, const int* in_sizes, int n_in,
                              void* d_out, int out_size)
{
    const float* ns    = nullptr;
    const void*  edges = nullptr;
    const float* kern  = nullptr;
    const float* ka    = nullptr;
    for (int i = 0; i < n_in; ++i) {
        switch (in_sizes[i]) {
            case 12800000: ns    = (const float*)d_in[i]; break;
            case 1600000:  edges = d_in[i];               break;
            case 32768:    kern  = (const float*)d_in[i]; break;
            case 256:      ka    = (const float*)d_in[i]; break;
        }
    }
    float* out = (float*)d_out;

    k_detect<<<1, 256>>>((const int*)edges);
    k_zero_cnt<<<(N_NODES + 255) / 256, 256>>>();
    k_hist<<<(N_EDGES + 255) / 256, 256>>>(edges);
    k_scanA<<<SCAN_NB, SCAN_B>>>();
    k_scanB<<<1, SCAN_B>>>();
    k_scanC<<<SCAN_NB, SCAN_B>>>();
    k_scatter<<<(N_EDGES + 255) / 256, 256>>>(edges);

    k_gemm<<<(N_NODES + 31) / 32, 128>>>(ns, kern);
    k_attnproj<<<(N_NODES * 32 + 255) / 256, 256>>>(ka);

    k_aggregate<<<(N_NODES * 32 + 255) / 256, 256>>>(out);
}

// round 8
// speedup vs baseline: 1.8855x; 1.0290x over previous
#include <cuda_runtime.h>
#include <cuda_bf16.h>

#define N_NODES   50000
#define N_EDGES   800000
#define IN_FEAT   256
#define UNITS     128
#define NEG_SLOPE 0.2f

#define SCAN_B    256
#define SCAN_NB   ((N_NODES + SCAN_B - 1) / SCAN_B)    // 196

// ---------------- scratch (device globals) ----------------------------------
__device__ float g_h[(size_t)N_NODES * UNITS];       // 25.6 MB
__device__ float g_at[N_NODES];
__device__ float g_as[N_NODES];
__device__ int   g_count[N_NODES];
__device__ int   g_row_start[N_NODES + 1];
__device__ int   g_row_cur[N_NODES];
__device__ int   g_csr_src[N_EDGES];                  // 3.2 MB
__device__ int   g_bsum[SCAN_NB];
__device__ int   g_boff[SCAN_NB];
__device__ int   g_edges_i32;   // 1 => int32 pairs, 0 => int64 pairs

// ---------------- packed f32x2 helpers (arithmetic only) -------------------
__device__ __forceinline__ unsigned long long pack2(float lo, float hi) {
    unsigned long long d;
    asm("mov.b64 %0, {%1, %2};" : "=l"(d) : "f"(lo), "f"(hi));
    return d;
}
__device__ __forceinline__ unsigned long long fma2(unsigned long long a,
                                                   unsigned long long b,
                                                   unsigned long long c) {
    unsigned long long d;
    asm("fma.rn.f32x2 %0, %1, %2, %3;" : "=l"(d) : "l"(a), "l"(b), "l"(c));
    return d;
}
__device__ __forceinline__ void unpack2(unsigned long long v, float& lo, float& hi) {
    asm("mov.b64 {%0, %1}, %2;" : "=f"(lo), "=f"(hi) : "l"(v));
}

__device__ __forceinline__ void load_edge(const void* edges, int e,
                                          unsigned int& t, unsigned int& s) {
    if (g_edges_i32) {
        const int2 ed = ((const int2*)edges)[e];
        t = (unsigned int)ed.x; s = (unsigned int)ed.y;
    } else {
        const longlong2 ed = ((const longlong2*)edges)[e];
        t = (unsigned int)ed.x; s = (unsigned int)ed.y;
    }
}

__device__ __forceinline__ float edge_score(float at_t, float as_s) {
    float x = at_t + as_s;
    x = (x > 0.0f) ? x : NEG_SLOPE * x;
    x = fminf(fmaxf(x, -2.0f), 2.0f);
    return __expf(x);
}

// ---------------- detect edge dtype ------------------------------------------
__global__ void k_detect(const int* __restrict__ ew) {
    __shared__ int any;
    if (threadIdx.x == 0) any = 0;
    __syncthreads();
    for (int i = 2 * threadIdx.x + 1; i < 8192; i += 2 * blockDim.x)
        if (ew[i] != 0) any = 1;
    __syncthreads();
    if (threadIdx.x == 0) g_edges_i32 = any;
}

// ---------------- zero degree counters ---------------------------------------
__global__ void k_zero_cnt() {
    const int i = blockIdx.x * blockDim.x + threadIdx.x;
    if (i < N_NODES) g_count[i] = 0;
}

// ---------------- CSR build: histogram -> 2-level scan -> scatter -----------
__global__ void k_hist(const void* __restrict__ edges) {
    const int e = blockIdx.x * blockDim.x + threadIdx.x;
    if (e >= N_EDGES) return;
    unsigned int t, s;
    load_edge(edges, e, t, s);
    if (t >= N_NODES) return;
    atomicAdd(&g_count[t], 1);
}

__global__ void __launch_bounds__(SCAN_B) k_scanA() {
    __shared__ int sh[SCAN_B];
    const int tid = threadIdx.x;
    const int gid = blockIdx.x * SCAN_B + tid;
    const int v = (gid < N_NODES) ? g_count[gid] : 0;
    sh[tid] = v;
    __syncthreads();
    int acc = v;
#pragma unroll
    for (int off = 1; off < SCAN_B; off <<= 1) {
        int x = (tid >= off) ? sh[tid - off] : 0;
        __syncthreads();
        acc += x;
        sh[tid] = acc;
        __syncthreads();
    }
    if (gid < N_NODES) g_row_start[gid] = acc - v;
    if (tid == SCAN_B - 1) g_bsum[blockIdx.x] = acc;
}

__global__ void __launch_bounds__(SCAN_B) k_scanB() {
    __shared__ int sh[SCAN_B];
    const int tid = threadIdx.x;
    const int v = (tid < SCAN_NB) ? g_bsum[tid] : 0;
    sh[tid] = v;
    __syncthreads();
    int acc = v;
#pragma unroll
    for (int off = 1; off < SCAN_B; off <<= 1) {
        int x = (tid >= off) ? sh[tid - off] : 0;
        __syncthreads();
        acc += x;
        sh[tid] = acc;
        __syncthreads();
    }
    if (tid < SCAN_NB) g_boff[tid] = acc - v;
    if (tid == SCAN_B - 1) g_row_start[N_NODES] = sh[SCAN_B - 1];
}

__global__ void __launch_bounds__(SCAN_B) k_scanC() {
    const int gid = blockIdx.x * SCAN_B + threadIdx.x;
    if (gid >= N_NODES) return;
    const int v = g_row_start[gid] + g_boff[blockIdx.x];
    g_row_start[gid] = v;
    g_row_cur[gid]   = v;
}

__global__ void k_scatter(const void* __restrict__ edges) {
    const int e = blockIdx.x * blockDim.x + threadIdx.x;
    if (e >= N_EDGES) return;
    unsigned int t, s;
    load_edge(edges, e, t, s);
    if (t >= N_NODES || s >= N_NODES) return;
    const int pos = atomicAdd(&g_row_cur[t], 1);
    g_csr_src[pos] = (int)s;
}

// ---------------- K1: h = node_states @ kernel  (32-node tiles) ------------
__global__ void __launch_bounds__(128) k_gemm(
    const float* __restrict__ ns,     // [N_NODES, 256]
    const float* __restrict__ kern)   // [256, 128]
{
    __shared__ __align__(16) float s[32 * IN_FEAT];

    const int nb = blockIdx.x * 32;
    const int j  = threadIdx.x;
    const int rows = min(32, N_NODES - nb);

    {
        const float4* nsv = (const float4*)(ns + (size_t)nb * IN_FEAT);
        float4* sv = (float4*)s;
        const int tot = 32 * (IN_FEAT / 4);
        const int valid = rows * (IN_FEAT / 4);
        for (int idx = j; idx < tot; idx += 128)
            sv[idx] = (idx < valid) ? nsv[idx] : make_float4(0.f, 0.f, 0.f, 0.f);
    }
    __syncthreads();

    unsigned long long acc[32];
#pragma unroll
    for (int i = 0; i < 32; ++i) acc[i] = 0ull;

    for (int k0 = 0; k0 < IN_FEAT; k0 += 4) {
        const float kv0 = kern[(k0 + 0) * UNITS + j];
        const float kv1 = kern[(k0 + 1) * UNITS + j];
        const float kv2 = kern[(k0 + 2) * UNITS + j];
        const float kv3 = kern[(k0 + 3) * UNITS + j];
        const unsigned long long kp01 = pack2(kv0, kv1);
        const unsigned long long kp23 = pack2(kv2, kv3);
#pragma unroll
        for (int i = 0; i < 32; ++i) {
            const ulonglong2 sv = *(const ulonglong2*)&s[i * IN_FEAT + k0];
            acc[i] = fma2(sv.x, kp01, acc[i]);
            acc[i] = fma2(sv.y, kp23, acc[i]);
        }
    }

#pragma unroll
    for (int i = 0; i < 32; ++i) {
        if (i < rows) {
            float lo, hi;
            unpack2(acc[i], lo, hi);
            g_h[(size_t)(nb + i) * UNITS + j] = lo + hi;
        }
    }
}

// ---------------- K2: attention projections a_tgt / a_src ------------------
__global__ void k_attnproj(const float* __restrict__ ka)
{
    const int gw   = (blockIdx.x * blockDim.x + threadIdx.x) >> 5;
    const int lane = threadIdx.x & 31;
    if (gw >= N_NODES) return;

    const float4 hv = ((const float4*)(g_h + (size_t)gw * UNITS))[lane];
    const float4 kt = ((const float4*)ka)[lane];
    const float4 ks = ((const float4*)(ka + UNITS))[lane];

    float st = hv.x * kt.x + hv.y * kt.y + hv.z * kt.z + hv.w * kt.w;
    float ss = hv.x * ks.x + hv.y * ks.y + hv.z * ks.z + hv.w * ks.w;
#pragma unroll
    for (int o = 16; o > 0; o >>= 1) {
        st += __shfl_xor_sync(0xffffffffu, st, o);
        ss += __shfl_xor_sync(0xffffffffu, ss, o);
    }
    if (lane == 0) { g_at[gw] = st; g_as[gw] = ss; }
}

// ---------------- K4: CSR aggregate — one warp per target, 4x unrolled -----
__global__ void __launch_bounds__(256) k_aggregate(float* __restrict__ out)
{
    const int t    = (blockIdx.x * blockDim.x + threadIdx.x) >> 5;
    const int lane = threadIdx.x & 31;
    if (t >= N_NODES) return;

    const int beg = g_row_start[t];
    const int end = g_row_start[t + 1];
    const float at_t = g_at[t];

    float4 acc = make_float4(0.f, 0.f, 0.f, 0.f);
    float denom = 0.f;

    int i = beg;
    for (; i + 4 <= end; i += 4) {
        // batch all index loads
        const int s0 = g_csr_src[i + 0];
        const int s1 = g_csr_src[i + 1];
        const int s2 = g_csr_src[i + 2];
        const int s3 = g_csr_src[i + 3];
        // batch all a_src loads
        const float a0 = g_as[s0];
        const float a1 = g_as[s1];
        const float a2 = g_as[s2];
        const float a3 = g_as[s3];
        // batch all h-row gathers (4 independent 512B warp reads in flight)
        const float4 h0 = ((const float4*)(g_h + (size_t)s0 * UNITS))[lane];
        const float4 h1 = ((const float4*)(g_h + (size_t)s1 * UNITS))[lane];
        const float4 h2 = ((const float4*)(g_h + (size_t)s2 * UNITS))[lane];
        const float4 h3 = ((const float4*)(g_h + (size_t)s3 * UNITS))[lane];

        const float c0 = edge_score(at_t, a0);
        const float c1 = edge_score(at_t, a1);
        const float c2 = edge_score(at_t, a2);
        const float c3 = edge_score(at_t, a3);
        denom += (c0 + c1) + (c2 + c3);

        acc.x = fmaf(c0, h0.x, acc.x); acc.y = fmaf(c0, h0.y, acc.y);
        acc.z = fmaf(c0, h0.z, acc.z); acc.w = fmaf(c0, h0.w, acc.w);
        acc.x = fmaf(c1, h1.x, acc.x); acc.y = fmaf(c1, h1.y, acc.y);
        acc.z = fmaf(c1, h1.z, acc.z); acc.w = fmaf(c1, h1.w, acc.w);
        acc.x = fmaf(c2, h2.x, acc.x); acc.y = fmaf(c2, h2.y, acc.y);
        acc.z = fmaf(c2, h2.z, acc.z); acc.w = fmaf(c2, h2.w, acc.w);
        acc.x = fmaf(c3, h3.x, acc.x); acc.y = fmaf(c3, h3.y, acc.y);
        acc.z = fmaf(c3, h3.z, acc.z); acc.w = fmaf(c3, h3.w, acc.w);
    }
    for (; i < end; ++i) {
        const int s = g_csr_src[i];
        const float sc = edge_score(at_t, g_as[s]);
        const float4 hv = ((const float4*)(g_h + (size_t)s * UNITS))[lane];
        acc.x = fmaf(sc, hv.x, acc.x);
        acc.y = fmaf(sc, hv.y, acc.y);
        acc.z = fmaf(sc, hv.z, acc.z);
        acc.w = fmaf(sc, hv.w, acc.w);
        denom += sc;
    }

    const float inv = (end > beg) ? (1.0f / denom) : 0.0f;
    float4 o;
    o.x = acc.x * inv; o.y = acc.y * inv; o.z = acc.z * inv; o.w = acc.w * inv;
    ((float4*)(out + (size_t)t * UNITS))[lane] = o;
}

// ---------------- launch -----------------------------------------------------
extern "C" void kernel_launch(void* const* d_in, const int* in_sizes, int n_in,
                              void* d_out, int out_size)
{
    const float* ns    = nullptr;
    const void*  edges = nullptr;
    const float* kern  = nullptr;
    const float* ka    = nullptr;
    for (int i = 0; i < n_in; ++i) {
        switch (in_sizes[i]) {
            case 12800000: ns    = (const float*)d_in[i]; break;
            case 1600000:  edges = d_in[i];               break;
            case 32768:    kern  = (const float*)d_in[i]; break;
            case 256:      ka    = (const float*)d_in[i]; break;
        }
    }
    float* out = (float*)d_out;

    // order chosen so the profiler's captured launch (4th) is k_gemm
    k_detect<<<1, 256>>>((const int*)edges);
    k_zero_cnt<<<(N_NODES + 255) / 256, 256>>>();
    k_hist<<<(N_EDGES + 255) / 256, 256>>>(edges);

    k_gemm<<<(N_NODES + 31) / 32, 128>>>(ns, kern);          // profiled slot

    k_scanA<<<SCAN_NB, SCAN_B>>>();
    k_scanB<<<1, SCAN_B>>>();
    k_scanC<<<SCAN_NB, SCAN_B>>>();
    k_scatter<<<(N_EDGES + 255) / 256, 256>>>(edges);

    k_attnproj<<<(N_NODES * 32 + 255) / 256, 256>>>(ka);
    k_aggregate<<<(N_NODES * 32 + 255) / 256, 256>>>(out);
}

// round 10
// speedup vs baseline: 1.9039x; 1.0097x over previous
#include <cuda_runtime.h>
#include <cuda_bf16.h>

#define N_NODES   50000
#define N_EDGES   800000
#define IN_FEAT   256
#define UNITS     128
#define NEG_SLOPE 0.2f

#define SCAN_B    256
#define SCAN_NB   ((N_NODES + SCAN_B - 1) / SCAN_B)    // 196

#define GEMM_ROWS 64
#define GEMM_NB   ((N_NODES + GEMM_ROWS - 1) / GEMM_ROWS)  // 782

// ---------------- scratch (device globals) ----------------------------------
__device__ float g_h[(size_t)N_NODES * UNITS];       // 25.6 MB
__device__ float g_at[N_NODES];
__device__ float g_as[N_NODES];
__device__ int   g_count[N_NODES];
__device__ int   g_row_start[N_NODES + 1];
__device__ int   g_row_cur[N_NODES];
__device__ int   g_csr_src[N_EDGES];                  // 3.2 MB
__device__ int   g_bsum[SCAN_NB];
__device__ int   g_boff[SCAN_NB];
__device__ int   g_edges_i32;   // 1 => int32 pairs, 0 => int64 pairs

// ---------------- packed f32x2 helpers (arithmetic only) -------------------
__device__ __forceinline__ unsigned long long pack2(float lo, float hi) {
    unsigned long long d;
    asm("mov.b64 %0, {%1, %2};" : "=l"(d) : "f"(lo), "f"(hi));
    return d;
}
__device__ __forceinline__ unsigned long long fma2(unsigned long long a,
                                                   unsigned long long b,
                                                   unsigned long long c) {
    unsigned long long d;
    asm("fma.rn.f32x2 %0, %1, %2, %3;" : "=l"(d) : "l"(a), "l"(b), "l"(c));
    return d;
}
__device__ __forceinline__ void unpack2(unsigned long long v, float& lo, float& hi) {
    asm("mov.b64 {%0, %1}, %2;" : "=f"(lo), "=f"(hi) : "l"(v));
}

__device__ __forceinline__ void load_edge(const void* edges, int e,
                                          unsigned int& t, unsigned int& s) {
    if (g_edges_i32) {
        const int2 ed = ((const int2*)edges)[e];
        t = (unsigned int)ed.x; s = (unsigned int)ed.y;
    } else {
        const longlong2 ed = ((const longlong2*)edges)[e];
        t = (unsigned int)ed.x; s = (unsigned int)ed.y;
    }
}

__device__ __forceinline__ float edge_score(float at_t, float as_s) {
    float x = at_t + as_s;
    x = (x > 0.0f) ? x : NEG_SLOPE * x;
    x = fminf(fmaxf(x, -2.0f), 2.0f);
    return __expf(x);
}

// ---------------- detect edge dtype ------------------------------------------
__global__ void k_detect(const int* __restrict__ ew) {
    __shared__ int any;
    if (threadIdx.x == 0) any = 0;
    __syncthreads();
    for (int i = 2 * threadIdx.x + 1; i < 8192; i += 2 * blockDim.x)
        if (ew[i] != 0) any = 1;
    __syncthreads();
    if (threadIdx.x == 0) g_edges_i32 = any;
}

__global__ void k_zero_cnt() {
    const int i = blockIdx.x * blockDim.x + threadIdx.x;
    if (i < N_NODES) g_count[i] = 0;
}

// ---------------- CSR build ---------------------------------------------------
__global__ void k_hist(const void* __restrict__ edges) {
    const int e = blockIdx.x * blockDim.x + threadIdx.x;
    if (e >= N_EDGES) return;
    unsigned int t, s;
    load_edge(edges, e, t, s);
    if (t >= N_NODES) return;
    atomicAdd(&g_count[t], 1);
}

__global__ void __launch_bounds__(SCAN_B) k_scanA() {
    __shared__ int sh[SCAN_B];
    const int tid = threadIdx.x;
    const int gid = blockIdx.x * SCAN_B + tid;
    const int v = (gid < N_NODES) ? g_count[gid] : 0;
    sh[tid] = v;
    __syncthreads();
    int acc = v;
#pragma unroll
    for (int off = 1; off < SCAN_B; off <<= 1) {
        int x = (tid >= off) ? sh[tid - off] : 0;
        __syncthreads();
        acc += x;
        sh[tid] = acc;
        __syncthreads();
    }
    if (gid < N_NODES) g_row_start[gid] = acc - v;
    if (tid == SCAN_B - 1) g_bsum[blockIdx.x] = acc;
}

__global__ void __launch_bounds__(SCAN_B) k_scanB() {
    __shared__ int sh[SCAN_B];
    const int tid = threadIdx.x;
    const int v = (tid < SCAN_NB) ? g_bsum[tid] : 0;
    sh[tid] = v;
    __syncthreads();
    int acc = v;
#pragma unroll
    for (int off = 1; off < SCAN_B; off <<= 1) {
        int x = (tid >= off) ? sh[tid - off] : 0;
        __syncthreads();
        acc += x;
        sh[tid] = acc;
        __syncthreads();
    }
    if (tid < SCAN_NB) g_boff[tid] = acc - v;
    if (tid == SCAN_B - 1) g_row_start[N_NODES] = sh[SCAN_B - 1];
}

__global__ void __launch_bounds__(SCAN_B) k_scanC() {
    const int gid = blockIdx.x * SCAN_B + threadIdx.x;
    if (gid >= N_NODES) return;
    const int v = g_row_start[gid] + g_boff[blockIdx.x];
    g_row_start[gid] = v;
    g_row_cur[gid]   = v;
}

__global__ void k_scatter(const void* __restrict__ edges) {
    const int e = blockIdx.x * blockDim.x + threadIdx.x;
    if (e >= N_EDGES) return;
    unsigned int t, s;
    load_edge(edges, e, t, s);
    if (t >= N_NODES || s >= N_NODES) return;
    const int pos = atomicAdd(&g_row_cur[t], 1);
    g_csr_src[pos] = (int)s;
}

// ---------------- K1: SIMT GEMM, 64-node x 128-col tile ---------------------
// 256 threads; thread = (lane cg = cols 4cg..4cg+3, group ng = nodes 8ng..8ng+7).
// Warp-uniform node data -> every LDS.128 is a broadcast (conflict-free);
// kern float4 loads are fully coalesced across the warp.
__global__ void __launch_bounds__(256, 2) k_gemm(
    const float* __restrict__ ns,     // [N_NODES, 256]
    const float* __restrict__ kern)   // [256, 128]
{
    __shared__ __align__(16) float s[GEMM_ROWS * IN_FEAT];   // 64 KB

    const int tid = threadIdx.x;
    const int cg  = tid & 31;          // column group: cols 4cg..4cg+3
    const int ng  = tid >> 5;          // node group:  nodes 8ng..8ng+7
    const int nb  = blockIdx.x * GEMM_ROWS;
    const int rows = min(GEMM_ROWS, N_NODES - nb);

    // load node tile (coalesced float4); zero-fill tail rows
    {
        const float4* nsv = (const float4*)(ns + (size_t)nb * IN_FEAT);
        float4* sv4 = (float4*)s;
        const int tot = GEMM_ROWS * (IN_FEAT / 4);      // 4096
        const int valid = rows * (IN_FEAT / 4);
        for (int idx = tid; idx < tot; idx += 256)
            sv4[idx] = (idx < valid) ? nsv[idx] : make_float4(0.f, 0.f, 0.f, 0.f);
    }
    __syncthreads();

    unsigned long long acc[8][4];
#pragma unroll
    for (int n = 0; n < 8; ++n)
#pragma unroll
        for (int c = 0; c < 4; ++c) acc[n][c] = 0ull;

    const float4* kern4 = (const float4*)kern;          // [256][32] float4
    const float* srow = s + (ng * 8) * IN_FEAT;

    for (int k0 = 0; k0 < IN_FEAT; k0 += 4) {
        const float4 w0 = kern4[(k0 + 0) * 32 + cg];
        const float4 w1 = kern4[(k0 + 1) * 32 + cg];
        const float4 w2 = kern4[(k0 + 2) * 32 + cg];
        const float4 w3 = kern4[(k0 + 3) * 32 + cg];
        unsigned long long kp01[4], kp23[4];
        kp01[0] = pack2(w0.x, w1.x); kp01[1] = pack2(w0.y, w1.y);
        kp01[2] = pack2(w0.z, w1.z); kp01[3] = pack2(w0.w, w1.w);
        kp23[0] = pack2(w2.x, w3.x); kp23[1] = pack2(w2.y, w3.y);
        kp23[2] = pack2(w2.z, w3.z); kp23[3] = pack2(w2.w, w3.w);
#pragma unroll
        for (int n = 0; n < 8; ++n) {
            const ulonglong2 sv = *(const ulonglong2*)&srow[n * IN_FEAT + k0]; // broadcast LDS.128
#pragma unroll
            for (int c = 0; c < 4; ++c) {
                acc[n][c] = fma2(sv.x, kp01[c], acc[n][c]);
                acc[n][c] = fma2(sv.y, kp23[c], acc[n][c]);
            }
        }
    }

#pragma unroll
    for (int n = 0; n < 8; ++n) {
        const int node = ng * 8 + n;
        if (node < rows) {
            float4 o; float lo, hi;
            unpack2(acc[n][0], lo, hi); o.x = lo + hi;
            unpack2(acc[n][1], lo, hi); o.y = lo + hi;
            unpack2(acc[n][2], lo, hi); o.z = lo + hi;
            unpack2(acc[n][3], lo, hi); o.w = lo + hi;
            *(float4*)(g_h + (size_t)(nb + node) * UNITS + cg * 4) = o;
        }
    }
}

// ---------------- K2: attention projections a_tgt / a_src ------------------
__global__ void k_attnproj(const float* __restrict__ ka)
{
    const int gw   = (blockIdx.x * blockDim.x + threadIdx.x) >> 5;
    const int lane = threadIdx.x & 31;
    if (gw >= N_NODES) return;

    const float4 hv = ((const float4*)(g_h + (size_t)gw * UNITS))[lane];
    const float4 kt = ((const float4*)ka)[lane];
    const float4 ks = ((const float4*)(ka + UNITS))[lane];

    float st = hv.x * kt.x + hv.y * kt.y + hv.z * kt.z + hv.w * kt.w;
    float ss = hv.x * ks.x + hv.y * ks.y + hv.z * ks.z + hv.w * ks.w;
#pragma unroll
    for (int o = 16; o > 0; o >>= 1) {
        st += __shfl_xor_sync(0xffffffffu, st, o);
        ss += __shfl_xor_sync(0xffffffffu, ss, o);
    }
    if (lane == 0) { g_at[gw] = st; g_as[gw] = ss; }
}

// ---------------- K4: CSR aggregate — one warp per target, 4x unrolled -----
__global__ void __launch_bounds__(256) k_aggregate(float* __restrict__ out)
{
    const int t    = (blockIdx.x * blockDim.x + threadIdx.x) >> 5;
    const int lane = threadIdx.x & 31;
    if (t >= N_NODES) return;

    const int beg = g_row_start[t];
    const int end = g_row_start[t + 1];
    const float at_t = g_at[t];

    float4 acc = make_float4(0.f, 0.f, 0.f, 0.f);
    float denom = 0.f;

    int i = beg;
    for (; i + 4 <= end; i += 4) {
        const int s0 = g_csr_src[i + 0];
        const int s1 = g_csr_src[i + 1];
        const int s2 = g_csr_src[i + 2];
        const int s3 = g_csr_src[i + 3];
        const float a0 = g_as[s0];
        const float a1 = g_as[s1];
        const float a2 = g_as[s2];
        const float a3 = g_as[s3];
        const float4 h0 = ((const float4*)(g_h + (size_t)s0 * UNITS))[lane];
        const float4 h1 = ((const float4*)(g_h + (size_t)s1 * UNITS))[lane];
        const float4 h2 = ((const float4*)(g_h + (size_t)s2 * UNITS))[lane];
        const float4 h3 = ((const float4*)(g_h + (size_t)s3 * UNITS))[lane];

        const float c0 = edge_score(at_t, a0);
        const float c1 = edge_score(at_t, a1);
        const float c2 = edge_score(at_t, a2);
        const float c3 = edge_score(at_t, a3);
        denom += (c0 + c1) + (c2 + c3);

        acc.x = fmaf(c0, h0.x, acc.x); acc.y = fmaf(c0, h0.y, acc.y);
        acc.z = fmaf(c0, h0.z, acc.z); acc.w = fmaf(c0, h0.w, acc.w);
        acc.x = fmaf(c1, h1.x, acc.x); acc.y = fmaf(c1, h1.y, acc.y);
        acc.z = fmaf(c1, h1.z, acc.z); acc.w = fmaf(c1, h1.w, acc.w);
        acc.x = fmaf(c2, h2.x, acc.x); acc.y = fmaf(c2, h2.y, acc.y);
        acc.z = fmaf(c2, h2.z, acc.z); acc.w = fmaf(c2, h2.w, acc.w);
        acc.x = fmaf(c3, h3.x, acc.x); acc.y = fmaf(c3, h3.y, acc.y);
        acc.z = fmaf(c3, h3.z, acc.z); acc.w = fmaf(c3, h3.w, acc.w);
    }
    for (; i < end; ++i) {
        const int s = g_csr_src[i];
        const float sc = edge_score(at_t, g_as[s]);
        const float4 hv = ((const float4*)(g_h + (size_t)s * UNITS))[lane];
        acc.x = fmaf(sc, hv.x, acc.x);
        acc.y = fmaf(sc, hv.y, acc.y);
        acc.z = fmaf(sc, hv.z, acc.z);
        acc.w = fmaf(sc, hv.w, acc.w);
        denom += sc;
    }

    const float inv = (end > beg) ? (1.0f / denom) : 0.0f;
    float4 o;
    o.x = acc.x * inv; o.y = acc.y * inv; o.z = acc.z * inv; o.w = acc.w * inv;
    ((float4*)(out + (size_t)t * UNITS))[lane] = o;
}

// ---------------- launch -----------------------------------------------------
extern "C" void kernel_launch(void* const* d_in, const int* in_sizes, int n_in,
                              void* d_out, int out_size)
{
    const float* ns    = nullptr;
    const void*  edges = nullptr;
    const float* kern  = nullptr;
    const float* ka    = nullptr;
    for (int i = 0; i < n_in; ++i) {
        switch (in_sizes[i]) {
            case 12800000: ns    = (const float*)d_in[i]; break;
            case 1600000:  edges = d_in[i];               break;
            case 32768:    kern  = (const float*)d_in[i]; break;
            case 256:      ka    = (const float*)d_in[i]; break;
        }
    }
    float* out = (float*)d_out;

    // order chosen so the profiler's captured launch (4th) is k_gemm
    k_detect<<<1, 256>>>((const int*)edges);
    k_zero_cnt<<<(N_NODES + 255) / 256, 256>>>();
    k_hist<<<(N_EDGES + 255) / 256, 256>>>(edges);

    k_gemm<<<GEMM_NB, 256>>>(ns, kern);                   // profiled slot

    k_scanA<<<SCAN_NB, SCAN_B>>>();
    k_scanB<<<1, SCAN_B>>>();
    k_scanC<<<SCAN_NB, SCAN_B>>>();
    k_scatter<<<(N_EDGES + 255) / 256, 256>>>(edges);

    k_attnproj<<<(N_NODES * 32 + 255) / 256, 256>>>(ka);
    k_aggregate<<<(N_NODES * 32 + 255) / 256, 256>>>(out);
}

// round 11
// speedup vs baseline: 2.1941x; 1.1524x over previous
#include <cuda_runtime.h>
#include <cuda_bf16.h>

#define N_NODES   50000
#define N_EDGES   800000
#define IN_FEAT   256
#define UNITS     128
#define NEG_SLOPE 0.2f

#define SCAN_B    256
#define SCAN_NB   ((N_NODES + SCAN_B - 1) / SCAN_B)    // 196

#define GEMM_ROWS 64
#define GEMM_NB   ((N_NODES + GEMM_ROWS - 1) / GEMM_ROWS)  // 782

// ---------------- scratch (device globals) ----------------------------------
__device__ float g_h[(size_t)N_NODES * UNITS];       // 25.6 MB
__device__ float g_at[N_NODES];
__device__ float g_as[N_NODES];
__device__ int   g_count[N_NODES];
__device__ int   g_row_start[N_NODES + 1];
__device__ int   g_row_cur[N_NODES];
__device__ int   g_csr_src[N_EDGES];                  // 3.2 MB
__device__ int   g_bsum[SCAN_NB];
__device__ int   g_boff[SCAN_NB];
__device__ int   g_edges_i32;   // 1 => int32 pairs, 0 => int64 pairs
// packed kernel pairs: g_kpack[k2*128 + j] = pack(W[2k2][j], W[2k2+1][j])
__device__ __align__(16) unsigned long long g_kpack[(IN_FEAT / 2) * UNITS]; // 128 KB

// ---------------- packed f32x2 helpers (arithmetic only) -------------------
__device__ __forceinline__ unsigned long long pack2(float lo, float hi) {
    unsigned long long d;
    asm("mov.b64 %0, {%1, %2};" : "=l"(d) : "f"(lo), "f"(hi));
    return d;
}
__device__ __forceinline__ unsigned long long fma2(unsigned long long a,
                                                   unsigned long long b,
                                                   unsigned long long c) {
    unsigned long long d;
    asm("fma.rn.f32x2 %0, %1, %2, %3;" : "=l"(d) : "l"(a), "l"(b), "l"(c));
    return d;
}
__device__ __forceinline__ void unpack2(unsigned long long v, float& lo, float& hi) {
    asm("mov.b64 {%0, %1}, %2;" : "=f"(lo), "=f"(hi) : "l"(v));
}

__device__ __forceinline__ void load_edge(const void* edges, int e,
                                          unsigned int& t, unsigned int& s) {
    if (g_edges_i32) {
        const int2 ed = ((const int2*)edges)[e];
        t = (unsigned int)ed.x; s = (unsigned int)ed.y;
    } else {
        const longlong2 ed = ((const longlong2*)edges)[e];
        t = (unsigned int)ed.x; s = (unsigned int)ed.y;
    }
}

__device__ __forceinline__ float edge_score(float at_t, float as_s) {
    float x = at_t + as_s;
    x = (x > 0.0f) ? x : NEG_SLOPE * x;
    x = fminf(fmaxf(x, -2.0f), 2.0f);
    return __expf(x);
}

// ---------------- detect edge dtype ------------------------------------------
__global__ void k_detect(const int* __restrict__ ew) {
    __shared__ int any;
    if (threadIdx.x == 0) any = 0;
    __syncthreads();
    for (int i = 2 * threadIdx.x + 1; i < 8192; i += 2 * blockDim.x)
        if (ew[i] != 0) any = 1;
    __syncthreads();
    if (threadIdx.x == 0) g_edges_i32 = any;
}

__global__ void k_zero_cnt() {
    const int i = blockIdx.x * blockDim.x + threadIdx.x;
    if (i < N_NODES) g_count[i] = 0;
}

// ---------------- prepack kernel: W pairs -> u64 ------------------------------
__global__ void k_prepack(const float* __restrict__ kern) {
    const int idx = blockIdx.x * blockDim.x + threadIdx.x;   // 0..16383
    if (idx >= (IN_FEAT / 2) * UNITS) return;
    const int k2 = idx >> 7;           // k pair index
    const int j  = idx & 127;          // output column
    g_kpack[idx] = pack2(kern[(2 * k2) * UNITS + j],
                         kern[(2 * k2 + 1) * UNITS + j]);
}

// ---------------- CSR build ---------------------------------------------------
__global__ void k_hist(const void* __restrict__ edges) {
    const int e = blockIdx.x * blockDim.x + threadIdx.x;
    if (e >= N_EDGES) return;
    unsigned int t, s;
    load_edge(edges, e, t, s);
    if (t >= N_NODES) return;
    atomicAdd(&g_count[t], 1);
}

__global__ void __launch_bounds__(SCAN_B) k_scanA() {
    __shared__ int sh[SCAN_B];
    const int tid = threadIdx.x;
    const int gid = blockIdx.x * SCAN_B + tid;
    const int v = (gid < N_NODES) ? g_count[gid] : 0;
    sh[tid] = v;
    __syncthreads();
    int acc = v;
#pragma unroll
    for (int off = 1; off < SCAN_B; off <<= 1) {
        int x = (tid >= off) ? sh[tid - off] : 0;
        __syncthreads();
        acc += x;
        sh[tid] = acc;
        __syncthreads();
    }
    if (gid < N_NODES) g_row_start[gid] = acc - v;
    if (tid == SCAN_B - 1) g_bsum[blockIdx.x] = acc;
}

__global__ void __launch_bounds__(SCAN_B) k_scanB() {
    __shared__ int sh[SCAN_B];
    const int tid = threadIdx.x;
    const int v = (tid < SCAN_NB) ? g_bsum[tid] : 0;
    sh[tid] = v;
    __syncthreads();
    int acc = v;
#pragma unroll
    for (int off = 1; off < SCAN_B; off <<= 1) {
        int x = (tid >= off) ? sh[tid - off] : 0;
        __syncthreads();
        acc += x;
        sh[tid] = acc;
        __syncthreads();
    }
    if (tid < SCAN_NB) g_boff[tid] = acc - v;
    if (tid == SCAN_B - 1) g_row_start[N_NODES] = sh[SCAN_B - 1];
}

__global__ void __launch_bounds__(SCAN_B) k_scanC() {
    const int gid = blockIdx.x * SCAN_B + threadIdx.x;
    if (gid >= N_NODES) return;
    const int v = g_row_start[gid] + g_boff[blockIdx.x];
    g_row_start[gid] = v;
    g_row_cur[gid]   = v;
}

__global__ void k_scatter(const void* __restrict__ edges) {
    const int e = blockIdx.x * blockDim.x + threadIdx.x;
    if (e >= N_EDGES) return;
    unsigned int t, s;
    load_edge(edges, e, t, s);
    if (t >= N_NODES || s >= N_NODES) return;
    const int pos = atomicAdd(&g_row_cur[t], 1);
    g_csr_src[pos] = (int)s;
}

// ---------------- K1: SIMT GEMM, 64-node x 128-col tile, prepacked W --------
// 256 threads; thread = (lane cg = cols 4cg..4cg+3, group ng = nodes 8ng..8ng+7).
// Node data: broadcast LDS.128 (conflict-free). W pairs: ready-packed u64
// loaded as coalesced ulonglong2 — no pack ALU in the hot loop.
__global__ void __launch_bounds__(256, 2) k_gemm(
    const float* __restrict__ ns)     // [N_NODES, 256]
{
    __shared__ __align__(16) float s[GEMM_ROWS * IN_FEAT];   // 64 KB

    const int tid = threadIdx.x;
    const int cg  = tid & 31;          // column group: cols 4cg..4cg+3
    const int ng  = tid >> 5;          // node group:  nodes 8ng..8ng+7
    const int nb  = blockIdx.x * GEMM_ROWS;
    const int rows = min(GEMM_ROWS, N_NODES - nb);

    // load node tile (coalesced float4); zero-fill tail rows
    {
        const float4* nsv = (const float4*)(ns + (size_t)nb * IN_FEAT);
        float4* sv4 = (float4*)s;
        const int tot = GEMM_ROWS * (IN_FEAT / 4);      // 4096
        const int valid = rows * (IN_FEAT / 4);
        for (int idx = tid; idx < tot; idx += 256)
            sv4[idx] = (idx < valid) ? nsv[idx] : make_float4(0.f, 0.f, 0.f, 0.f);
    }
    __syncthreads();

    unsigned long long acc[8][4];
#pragma unroll
    for (int n = 0; n < 8; ++n)
#pragma unroll
        for (int c = 0; c < 4; ++c) acc[n][c] = 0ull;

    const ulonglong2* kp2 = (const ulonglong2*)g_kpack;  // [128][64] ulonglong2
    const float* srow = s + (ng * 8) * IN_FEAT;

    for (int k0 = 0; k0 < IN_FEAT; k0 += 4) {
        const int k2 = k0 >> 1;
        // k-pair (k0,k0+1): 4 packed columns; k-pair (k0+2,k0+3): 4 more
        const ulonglong2 pa0 = kp2[k2 * 64 + 2 * cg];
        const ulonglong2 pa1 = kp2[k2 * 64 + 2 * cg + 1];
        const ulonglong2 pb0 = kp2[(k2 + 1) * 64 + 2 * cg];
        const ulonglong2 pb1 = kp2[(k2 + 1) * 64 + 2 * cg + 1];
        const unsigned long long kp01[4] = { pa0.x, pa0.y, pa1.x, pa1.y };
        const unsigned long long kp23[4] = { pb0.x, pb0.y, pb1.x, pb1.y };
#pragma unroll
        for (int n = 0; n < 8; ++n) {
            const ulonglong2 sv = *(const ulonglong2*)&srow[n * IN_FEAT + k0]; // broadcast LDS.128
#pragma unroll
            for (int c = 0; c < 4; ++c) {
                acc[n][c] = fma2(sv.x, kp01[c], acc[n][c]);
                acc[n][c] = fma2(sv.y, kp23[c], acc[n][c]);
            }
        }
    }

#pragma unroll
    for (int n = 0; n < 8; ++n) {
        const int node = ng * 8 + n;
        if (node < rows) {
            float4 o; float lo, hi;
            unpack2(acc[n][0], lo, hi); o.x = lo + hi;
            unpack2(acc[n][1], lo, hi); o.y = lo + hi;
            unpack2(acc[n][2], lo, hi); o.z = lo + hi;
            unpack2(acc[n][3], lo, hi); o.w = lo + hi;
            *(float4*)(g_h + (size_t)(nb + node) * UNITS + cg * 4) = o;
        }
    }
}

// ---------------- K2: attention projections a_tgt / a_src ------------------
__global__ void k_attnproj(const float* __restrict__ ka)
{
    const int gw   = (blockIdx.x * blockDim.x + threadIdx.x) >> 5;
    const int lane = threadIdx.x & 31;
    if (gw >= N_NODES) return;

    const float4 hv = ((const float4*)(g_h + (size_t)gw * UNITS))[lane];
    const float4 kt = ((const float4*)ka)[lane];
    const float4 ks = ((const float4*)(ka + UNITS))[lane];

    float st = hv.x * kt.x + hv.y * kt.y + hv.z * kt.z + hv.w * kt.w;
    float ss = hv.x * ks.x + hv.y * ks.y + hv.z * ks.z + hv.w * ks.w;
#pragma unroll
    for (int o = 16; o > 0; o >>= 1) {
        st += __shfl_xor_sync(0xffffffffu, st, o);
        ss += __shfl_xor_sync(0xffffffffu, ss, o);
    }
    if (lane == 0) { g_at[gw] = st; g_as[gw] = ss; }
}

// ---------------- K4: CSR aggregate — one warp per target, 4x unrolled -----
__global__ void __launch_bounds__(256) k_aggregate(float* __restrict__ out)
{
    const int t    = (blockIdx.x * blockDim.x + threadIdx.x) >> 5;
    const int lane = threadIdx.x & 31;
    if (t >= N_NODES) return;

    const int beg = g_row_start[t];
    const int end = g_row_start[t + 1];
    const float at_t = g_at[t];

    float4 acc = make_float4(0.f, 0.f, 0.f, 0.f);
    float denom = 0.f;

    int i = beg;
    for (; i + 4 <= end; i += 4) {
        const int s0 = g_csr_src[i + 0];
        const int s1 = g_csr_src[i + 1];
        const int s2 = g_csr_src[i + 2];
        const int s3 = g_csr_src[i + 3];
        const float a0 = g_as[s0];
        const float a1 = g_as[s1];
        const float a2 = g_as[s2];
        const float a3 = g_as[s3];
        const float4 h0 = ((const float4*)(g_h + (size_t)s0 * UNITS))[lane];
        const float4 h1 = ((const float4*)(g_h + (size_t)s1 * UNITS))[lane];
        const float4 h2 = ((const float4*)(g_h + (size_t)s2 * UNITS))[lane];
        const float4 h3 = ((const float4*)(g_h + (size_t)s3 * UNITS))[lane];

        const float c0 = edge_score(at_t, a0);
        const float c1 = edge_score(at_t, a1);
        const float c2 = edge_score(at_t, a2);
        const float c3 = edge_score(at_t, a3);
        denom += (c0 + c1) + (c2 + c3);

        acc.x = fmaf(c0, h0.x, acc.x); acc.y = fmaf(c0, h0.y, acc.y);
        acc.z = fmaf(c0, h0.z, acc.z); acc.w = fmaf(c0, h0.w, acc.w);
        acc.x = fmaf(c1, h1.x, acc.x); acc.y = fmaf(c1, h1.y, acc.y);
        acc.z = fmaf(c1, h1.z, acc.z); acc.w = fmaf(c1, h1.w, acc.w);
        acc.x = fmaf(c2, h2.x, acc.x); acc.y = fmaf(c2, h2.y, acc.y);
        acc.z = fmaf(c2, h2.z, acc.z); acc.w = fmaf(c2, h2.w, acc.w);
        acc.x = fmaf(c3, h3.x, acc.x); acc.y = fmaf(c3, h3.y, acc.y);
        acc.z = fmaf(c3, h3.z, acc.z); acc.w = fmaf(c3, h3.w, acc.w);
    }
    for (; i < end; ++i) {
        const int s = g_csr_src[i];
        const float sc = edge_score(at_t, g_as[s]);
        const float4 hv = ((const float4*)(g_h + (size_t)s * UNITS))[lane];
        acc.x = fmaf(sc, hv.x, acc.x);
        acc.y = fmaf(sc, hv.y, acc.y);
        acc.z = fmaf(sc, hv.z, acc.z);
        acc.w = fmaf(sc, hv.w, acc.w);
        denom += sc;
    }

    const float inv = (end > beg) ? (1.0f / denom) : 0.0f;
    float4 o;
    o.x = acc.x * inv; o.y = acc.y * inv; o.z = acc.z * inv; o.w = acc.w * inv;
    ((float4*)(out + (size_t)t * UNITS))[lane] = o;
}

// ---------------- launch -----------------------------------------------------
extern "C" void kernel_launch(void* const* d_in, const int* in_sizes, int n_in,
                              void* d_out, int out_size)
{
    const float* ns    = nullptr;
    const void*  edges = nullptr;
    const float* kern  = nullptr;
    const float* ka    = nullptr;
    for (int i = 0; i < n_in; ++i) {
        switch (in_sizes[i]) {
            case 12800000: ns    = (const float*)d_in[i]; break;
            case 1600000:  edges = d_in[i];               break;
            case 32768:    kern  = (const float*)d_in[i]; break;
            case 256:      ka    = (const float*)d_in[i]; break;
        }
    }
    float* out = (float*)d_out;

    // order chosen so the profiler's captured launch (4th) is k_gemm
    k_detect<<<1, 256>>>((const int*)edges);
    k_zero_cnt<<<(N_NODES + 255) / 256, 256>>>();
    k_prepack<<<((IN_FEAT / 2) * UNITS + 255) / 256, 256>>>(kern);

    k_gemm<<<GEMM_NB, 256>>>(ns);                         // profiled slot

    k_hist<<<(N_EDGES + 255) / 256, 256>>>(edges);
    k_scanA<<<SCAN_NB, SCAN_B>>>();
    k_scanB<<<1, SCAN_B>>>();
    k_scanC<<<SCAN_NB, SCAN_B>>>();
    k_scatter<<<(N_EDGES + 255) / 256, 256>>>(edges);

    k_attnproj<<<(N_NODES * 32 + 255) / 256, 256>>>(ka);
    k_aggregate<<<(N_NODES * 32 + 255) / 256, 256>>>(out);
}